// round 17
// baseline (speedup 1.0000x reference)
#include <cuda_runtime.h>
#include <cuda_fp16.h>
#include <cstdint>

// ============================================================================
// CoCov via mma.sync (HMMA) fp16 single-pass, input-shift formulation.
// Half-tile CTAs: each 128-thread CTA computes 128 pixels x 64 co of a tile
// (h = 0/1 selects rows 0-7 / 8-15). 3 CTAs/SM (12 warps) for latency cover.
// A staged as 10-row slices (rows 8h-1..8h+8) of pre-converted swizzled fp16
// panels via cp.async, double-buffered, ONE barrier per kt. B in uint4-packed
// mma-fragment order, per-warp __ldg with k16 register ping-pong. Block-
// uniform zero-kt skip; tap loop unrolled x3.
// ============================================================================

// B packed: [T=kt*9+tap][k16 4][np 4][lane 32] uint4  (.xy nt=2np, .zw nt=2np+1)
__device__ uint4 g_bw4[81 * 512];
// pre-converted A panels: [b*256 + u1*16 + u2][pix 256][128B swizzled row]
__device__ uint4 g_bA[2048 * 2048];

// preprocessing: every block converts its A panel; first blocks also
// rearrange the weights (81*512 uint4 elements).
__global__ void __launch_bounds__(256) prep_kernel(const float* __restrict__ inp,
                                                   const float* __restrict__ K) {
    extern __shared__ char sm[];
    const int tid = threadIdx.x;
    const int u2 = blockIdx.x, u1 = blockIdx.y, b = blockIdx.z;
    const int bid = (b * 16 + u1) * 16 + u2;

    {   // ---- weight rearrange ----
        int gid = bid * 256 + tid;
        if (gid < 81 * 512) {
            int lane = gid & 31;
            int np   = (gid >> 5) & 3;
            int k16  = (gid >> 7) & 3;
            int T    = gid >> 9;
            int tp = T % 9, kt = T / 9;
            int k0 = k16 * 16 + (lane & 3) * 2;
            #pragma unroll
            for (int hh = 0; hh < 2; hh++) {
                int co = (2 * np + hh) * 8 + (lane >> 2);
                const float* Kc = K + ((kt * 64 + co) * 64) * 9 + tp; // [k][co][ci][9]
                __half2 lo2(__float2half(Kc[(size_t)k0 * 9]),
                            __float2half(Kc[(size_t)(k0 + 1) * 9]));
                __half2 hi2(__float2half(Kc[(size_t)(k0 + 8) * 9]),
                            __float2half(Kc[(size_t)(k0 + 9) * 9]));
                if (hh == 0) { g_bw4[gid].x = *(uint32_t*)&lo2; g_bw4[gid].y = *(uint32_t*)&hi2; }
                else         { g_bw4[gid].z = *(uint32_t*)&lo2; g_bw4[gid].w = *(uint32_t*)&hi2; }
            }
        }
    }

    // ---- A panel convert: fp32 -> fp16, swizzled 128B rows ----
    const float* src = inp + (size_t)b * 64 * 65536
                     + (size_t)(u1 * 16 + (tid >> 4)) * 256 + u2 * 16 + (tid & 15);
    const uint32_t rowa = tid * 128;
    #pragma unroll
    for (int ch = 0; ch < 8; ch++) {
        uint32_t hi4[4];
        #pragma unroll
        for (int e = 0; e < 4; e++) {
            float x0 = __ldg(src + (size_t)(ch * 8 + 2 * e) * 65536);
            float x1 = __ldg(src + (size_t)(ch * 8 + 2 * e + 1) * 65536);
            __half2 hp(__float2half(x0), __float2half(x1));
            hi4[e] = *(uint32_t*)&hp;
        }
        uint32_t off = rowa + ((ch ^ (tid & 7)) << 4);
        *(uint4*)(sm + off) = make_uint4(hi4[0], hi4[1], hi4[2], hi4[3]);
    }
    __syncthreads();
    uint4* dst = g_bA + (size_t)bid * 2048;
    const uint4* s4 = (const uint4*)sm;
    #pragma unroll
    for (int k = 0; k < 8; k++) dst[tid + k * 256] = s4[tid + k * 256];
}

__device__ __forceinline__ uint32_t smem_u32(const void* p) {
    uint32_t a;
    asm("{ .reg .u64 t; cvta.to.shared.u64 t, %1; cvt.u32.u64 %0, t; }" : "=r"(a) : "l"(p));
    return a;
}
__device__ __forceinline__ void ldsm_x4(uint32_t* r, uint32_t addr) {
    asm volatile("ldmatrix.sync.aligned.m8n8.x4.shared.b16 {%0,%1,%2,%3}, [%4];"
                 : "=r"(r[0]), "=r"(r[1]), "=r"(r[2]), "=r"(r[3]) : "r"(addr));
}
__device__ __forceinline__ void mma16816(float* d, const uint32_t* a, const uint32_t* b) {
    asm volatile(
        "mma.sync.aligned.m16n8k16.row.col.f32.f16.f16.f32 "
        "{%0,%1,%2,%3}, {%4,%5,%6,%7}, {%8,%9}, {%0,%1,%2,%3};"
        : "+f"(d[0]), "+f"(d[1]), "+f"(d[2]), "+f"(d[3])
        : "r"(a[0]), "r"(a[1]), "r"(a[2]), "r"(a[3]), "r"(b[0]), "r"(b[1]));
}

#define CP16(dst, src, sz) \
    asm volatile("cp.async.cg.shared.global [%0], [%1], 16, %2;" \
                 :: "r"(dst), "l"(src), "r"(sz) : "memory")
#define CPCOMMIT() asm volatile("cp.async.commit_group;" ::: "memory")
#define CPWAIT0()  asm volatile("cp.async.wait_group 0;" ::: "memory")

// smem: A slice bufs: 2 x [161 rows][128B] (row 160 = zeros) = 41216,
// epilogue reuses smem as acc [pix 128][72] fp32 = 36864 -> SM_TOTAL = 41216
#define ABUF_SZ  20608              // 161 * 128
#define SM_TOTAL 41216              // 3 CTAs/SM

__global__ void __launch_bounds__(128, 3)
cocov_mma_kernel(float* __restrict__ out) {
    extern __shared__ char smem[];
    const uint32_t sb = smem_u32(smem);

    const int tid = threadIdx.x;
    const int lane = tid & 31;
    const int wid = tid >> 5;              // 0..3, each warp: 32 pixels
    const int t2 = blockIdx.x, t1 = blockIdx.y;
    const int b  = blockIdx.z >> 1;
    const int h  = blockIdx.z & 1;         // half-tile: rows 8h..8h+7

    // zero rows (row 160 of each A buf), written once (published by kt=0 barrier)
    if (tid < 64) {
        int buf = tid >> 5;
        *(float*)(smem + buf * ABUF_SZ + 160 * 128 + (tid & 31) * 4) = 0.f;
    }

    auto kt_valid = [&](int kt) -> bool {
        const int tt1 = t1 + kt / 3 - 1;
        const int tt2 = t2 + kt % 3 - 1;
        return ((unsigned)tt1 < 16u) && ((unsigned)tt2 < 16u);
    };

    // stage 10-row slice (tile rows 8h-1 .. 8h+8) of panel kt
    auto prefetch_A = [&](int kt) {
        const int tt1 = t1 + kt / 3 - 1;
        const int tt2 = t2 + kt % 3 - 1;
        const bool v = ((unsigned)tt1 < 16u) && ((unsigned)tt2 < 16u);
        const char* srcp = (const char*)(g_bA
            + (size_t)(b * 256 + (v ? tt1 * 16 + tt2 : 0)) * 2048);
        const uint32_t abase = sb + (kt & 1) * ABUF_SZ;
        #pragma unroll
        for (int it = 0; it < 10; it++) {
            int e  = tid + it * 128;          // chunk 0..1279 (16B chunks)
            int lp = e >> 3;                  // local pixel 0..159
            int si = (lp >> 4) + 8 * h - 1;   // tile row
            bool ok = v && ((unsigned)si < 16u);
            int srcoff = ok ? ((si * 16 + (lp & 15)) * 128 + (e & 7) * 16) : 0;
            CP16(abase + e * 16, srcp + srcoff, ok ? 16 : 0);
        }
    };

    // B fragment loader: tap T, k-step k16 -> 4 uint4 (nt pairs)
    const uint4* bbase_g = g_bw4 + lane;
    auto load_bf = [&](int T, int k16, uint4* bf) {
        const uint4* p = bbase_g + (size_t)T * 512 + k16 * 128;
        #pragma unroll
        for (int np = 0; np < 4; np++) bf[np] = __ldg(p + np * 32);
    };

    // ldmatrix lane addressing pieces
    const int a_kc_lane = (lane >> 4);
    const int jlane     = lane & 15;

    float d[2][8][4];
    #pragma unroll
    for (int mt = 0; mt < 2; mt++)
        #pragma unroll
        for (int nt = 0; nt < 8; nt++)
            #pragma unroll
            for (int r = 0; r < 4; r++) d[mt][nt][r] = 0.f;

    uint4 bfA[4], bfB[4];

    // prologue
    prefetch_A(0); CPCOMMIT();
    load_bf(0, 0, bfA);

    #pragma unroll 1
    for (int kt = 0; kt < 9; kt++) {
        CPWAIT0();
        __syncthreads();                       // publish A(kt) (+zero rows at kt=0)
        if (kt < 8) { prefetch_A(kt + 1); CPCOMMIT(); }

        // block-uniform skip: whole neighbor tile out of grid -> slice is zero
        if (!kt_valid(kt)) {
            if (kt < 8) load_bf((kt + 1) * 9, 0, bfA);
            continue;
        }

        const uint32_t abase = sb + (kt & 1) * ABUF_SZ;

        #pragma unroll 3
        for (int tp = 0; tp < 9; tp++) {
            const int T = kt * 9 + tp;

            // shifted A row addresses for this tap (zero row 160 when invalid)
            const int dh = tp / 3 - 1, dw = tp % 3 - 1;
            const int sj = jlane + dw;
            const bool jv = (unsigned)sj < 16u;
            uint32_t rowbase[2];
            int key[2];
            #pragma unroll
            for (int mt = 0; mt < 2; mt++) {
                int si = 8 * h + wid * 2 + mt + dh;           // tile row
                int srow = (jv && ((unsigned)si < 16u))
                         ? (si - 8 * h + 1) * 16 + sj : 160;  // slice-local row
                rowbase[mt] = abase + (uint32_t)srow * 128;
                key[mt] = srow & 7;
            }

            const int Tn = (T < 80) ? T + 1 : T;
            #pragma unroll
            for (int k16 = 0; k16 < 4; k16++) {
                uint4* cur = (k16 & 1) ? bfB : bfA;
                uint4* nxt = (k16 & 1) ? bfA : bfB;
                if (k16 < 3) load_bf(T, k16 + 1, nxt);
                else         load_bf(Tn, 0, nxt);

                const int kc = k16 * 2 + a_kc_lane;
                uint32_t a[2][4];
                #pragma unroll
                for (int mt = 0; mt < 2; mt++)
                    ldsm_x4(a[mt], rowbase[mt] + ((kc ^ key[mt]) << 4));
                #pragma unroll
                for (int mt = 0; mt < 2; mt++)
                    #pragma unroll
                    for (int nt = 0; nt < 8; nt++)
                        mma16816(d[mt][nt], a[mt],
                                 (const uint32_t*)&cur[nt >> 1] + ((nt & 1) << 1));
            }
        }
    }

    // ---- epilogue: fragments -> smem acc [128][72] -> coalesced global ----
    __syncthreads();
    float* accS = (float*)smem;
    #pragma unroll
    for (int mt = 0; mt < 2; mt++) {
        #pragma unroll
        for (int r = 0; r < 4; r++) {
            const int p = wid * 32 + mt * 16 + (lane >> 2) + ((r >> 1) & 1) * 8;
            float* dst = accS + p * 72 + (lane & 3) * 2 + (r & 1);
            #pragma unroll
            for (int nt = 0; nt < 8; nt++)
                dst[nt * 8] = d[mt][nt][r];
        }
    }
    __syncthreads();
    {
        const size_t obase = ((size_t)(b * 64) * 256
                              + (size_t)(t1 * 16 + 8 * h + (tid >> 4))) * 256
                             + t2 * 16 + (tid & 15);
        const float* arow = accS + tid * 72;
        #pragma unroll 8
        for (int co = 0; co < 64; co++)
            out[obase + (size_t)co * 65536] = arow[co];
    }
}

extern "C" void kernel_launch(void* const* d_in, const int* in_sizes, int n_in,
                              void* d_out, int out_size) {
    const float* inp = (const float*)d_in[0];   // (8, 64, 256, 256) fp32
    const float* ker = (const float*)d_in[1];   // (9, 64, 64, 3, 3) fp32
    float* out = (float*)d_out;                 // (8, 64, 256, 256) fp32

    cudaFuncSetAttribute(prep_kernel,
                         cudaFuncAttributeMaxDynamicSharedMemorySize, 32768);
    dim3 pgrid(16, 16, 8);   // (u2, u1, b)
    prep_kernel<<<pgrid, 256, 32768>>>(inp, ker);

    cudaFuncSetAttribute(cocov_mma_kernel,
                         cudaFuncAttributeMaxDynamicSharedMemorySize, SM_TOTAL);
    dim3 grid(16, 16, 16);   // (t2, t1, b*2+h)
    cocov_mma_kernel<<<grid, 128, SM_TOTAL>>>(out);
}